// round 2
// baseline (speedup 1.0000x reference)
#include <cuda_runtime.h>
#include <math.h>

#define BB 8
#define TT 262144
#define CC 8
#define KK 50
#define TS 2048
#define NT 256

// Scratch: ping-pong activation buffers [B][T][C] + normalized weights.
__device__ float g_bufA[(size_t)BB * TT * CC];
__device__ float g_bufB[(size_t)BB * TT * CC];
__device__ float g_w[(size_t)17 * KK * CC * CC];  // [layer][k][o][c], tap-reversed
__device__ float g_w0[CC * KK];                   // [o][k], tap-reversed

// ---------------------------------------------------------------------------
// packed fp32x2 FMA (sm_100+): d = a*b + d elementwise on two f32 lanes
// ---------------------------------------------------------------------------
__device__ __forceinline__ void ffma2(unsigned long long& d,
                                      unsigned long long a,
                                      unsigned long long b) {
    asm("fma.rn.f32x2 %0, %1, %2, %0;" : "+l"(d) : "l"(a), "l"(b));
}

// ---------------------------------------------------------------------------
// Weight-norm prep: w[o,c,k] = g[o] * v[o,c,k] / ||v[o,:,:]||, stored
// tap-reversed ([k] slot holds original tap K-1-k) because lax.conv is
// cross-correlation with left-pad (K-1)*d.
// ---------------------------------------------------------------------------
__global__ void prep_weights(const float* __restrict__ v0,
                             const float* __restrict__ g0,
                             const float* __restrict__ vs,
                             const float* __restrict__ gs) {
    __shared__ float rnorm[CC];
    int l = blockIdx.x;
    int tid = threadIdx.x;
    if (l == 0) {
        if (tid < CC) {
            float s = 0.f;
            for (int k = 0; k < KK; k++) {
                float v = v0[tid * KK + k];
                s += v * v;
            }
            rnorm[tid] = rsqrtf(s);
        }
        __syncthreads();
        for (int idx = tid; idx < CC * KK; idx += blockDim.x) {
            int o = idx / KK, k = idx % KK;
            g_w0[o * KK + k] = g0[o] * v0[o * KK + (KK - 1 - k)] * rnorm[o];
        }
    } else {
        int i = l - 1;
        const float* v = vs + (size_t)i * CC * CC * KK;
        if (tid < CC) {
            float s = 0.f;
            for (int j = 0; j < CC * KK; j++) {
                float x = v[tid * CC * KK + j];
                s += x * x;
            }
            rnorm[tid] = rsqrtf(s);
        }
        __syncthreads();
        float* wout = g_w + (size_t)i * KK * CC * CC;
        for (int idx = tid; idx < KK * CC * CC; idx += blockDim.x) {
            int k = idx / (CC * CC);
            int r = idx % (CC * CC);
            int o = r / CC, c = r % CC;
            wout[idx] = gs[i * CC + o] * v[(o * CC + c) * KK + (KK - 1 - k)] * rnorm[o];
        }
    }
}

// ---------------------------------------------------------------------------
// Layer 0: C_in = 1 (x broadcast), dilation 1. Writes g_bufA [B][T][C].
// ---------------------------------------------------------------------------
__global__ void __launch_bounds__(NT) layer0_kernel(
    const float* __restrict__ x, const float* __restrict__ b0,
    const float* __restrict__ gw0, const float* __restrict__ gb0) {
    __shared__ float s_x[TS + KK];
    __shared__ float s_w[CC * KK];
    __shared__ float s_b[CC], s_gb[CC], s_gw[CC * CC];
    int b = blockIdx.y;
    int t0 = blockIdx.x * TS;
    int tid = threadIdx.x;
    for (int i = tid; i < CC * KK; i += NT) s_w[i] = g_w0[i];
    for (int i = tid; i < CC * CC; i += NT) s_gw[i] = gw0[i];
    if (tid < CC) { s_b[tid] = b0[tid]; s_gb[tid] = gb0[tid]; }
    const float* xb = x + (size_t)b * TT;
    for (int i = tid; i < TS + KK - 1; i += NT) {
        int t = t0 - (KK - 1) + i;
        s_x[i] = (t >= 0) ? xb[t] : 0.f;
    }
    __syncthreads();
    float* hout = g_bufA + (size_t)b * TT * CC;
    for (int p = 0; p < TS / NT; p++) {
        int tl = p * NT + tid;
        int j = tl + KK - 1;
        float out[CC];
#pragma unroll
        for (int o = 0; o < CC; o++) out[o] = s_b[o];
#pragma unroll 2
        for (int k = 0; k < KK; k++) {
            float xv = s_x[j - k];
#pragma unroll
            for (int o = 0; o < CC; o++) out[o] += s_w[o * KK + k] * xv;
        }
        float res = s_x[j];
        float h8[CC];
#pragma unroll
        for (int o = 0; o < CC; o++) {
            float g = s_gb[o];
#pragma unroll
            for (int c = 0; c < CC; c++) g += s_gw[o * CC + c] * out[c];
            h8[o] = tanhf(out[o]) / (1.f + expf(-g)) + res;
        }
        float4* dst = (float4*)(hout + (size_t)(t0 + tl) * CC);
        dst[0] = make_float4(h8[0], h8[1], h8[2], h8[3]);
        dst[1] = make_float4(h8[4], h8[5], h8[6], h8[7]);
    }
}

// ---------------------------------------------------------------------------
// Layers 1..17: fused dilated causal conv (C=8 in/out, K=50) + 1x1 gating +
// tanh*sigmoid + residual. f32x2-packed over channel pairs (reduction dim).
// ---------------------------------------------------------------------------
__global__ void __launch_bounds__(NT) layer_kernel(
    const float* __restrict__ hin, float* __restrict__ hout, int li,
    const float* __restrict__ bias, const float* __restrict__ gw,
    const float* __restrict__ gb, int d) {
    extern __shared__ float smem[];
    float* s_w = smem;               // KK*64  [k][o][c]
    float* s_gw = s_w + KK * 64;     // 64
    float* s_b = s_gw + 64;          // 8
    float* s_gb = s_b + 8;           // 8
    float* s_h = s_gb + 8;           // (TS+halo)*8, 16B-aligned (offset 3280 floats)

    int halo = 49 * d;
    int tid = threadIdx.x;
    int b = blockIdx.y;
    int t0 = blockIdx.x * TS;

    const float* wsrc = g_w + (size_t)li * KK * 64;
    for (int i = tid; i < KK * 64; i += NT) s_w[i] = wsrc[i];
    for (int i = tid; i < 64; i += NT) s_gw[i] = gw[i];
    if (tid < 8) { s_b[tid] = bias[tid]; s_gb[tid] = gb[tid]; }

    const float* hb = hin + (size_t)b * TT * CC;
    int total4 = (TS + halo) * 2;
    for (int i = tid; i < total4; i += NT) {
        int j = i >> 1, half = i & 1;
        int t = t0 - halo + j;
        float4 v = make_float4(0.f, 0.f, 0.f, 0.f);
        if (t >= 0) v = *(const float4*)(hb + (size_t)t * CC + half * 4);
        ((float4*)s_h)[i] = v;
    }
    __syncthreads();

    float* ho = hout + (size_t)b * TT * CC;
    for (int p = 0; p < TS / NT; p++) {
        int tl = p * NT + tid;
        int j = tl + halo;
        unsigned long long acc[8];
#pragma unroll
        for (int o = 0; o < 8; o++) acc[o] = 0ULL;

        const float4* hrow = (const float4*)s_h + (size_t)j * 2;
#pragma unroll 2
        for (int k = 0; k < KK; k++) {
            const float4* hr = hrow - k * (2 * d);
            float4 ha = hr[0], hc = hr[1];
            unsigned long long h01, h23, h45, h67;
            memcpy(&h01, &ha.x, 8);
            memcpy(&h23, &ha.z, 8);
            memcpy(&h45, &hc.x, 8);
            memcpy(&h67, &hc.z, 8);
            const float4* wk = (const float4*)(s_w + k * 64);
#pragma unroll
            for (int o = 0; o < 8; o++) {
                float4 wa = wk[o * 2], wb = wk[o * 2 + 1];
                unsigned long long w01, w23, w45, w67;
                memcpy(&w01, &wa.x, 8);
                memcpy(&w23, &wa.z, 8);
                memcpy(&w45, &wb.x, 8);
                memcpy(&w67, &wb.z, 8);
                ffma2(acc[o], h01, w01);
                ffma2(acc[o], h23, w23);
                ffma2(acc[o], h45, w45);
                ffma2(acc[o], h67, w67);
            }
        }

        float out[8];
#pragma unroll
        for (int o = 0; o < 8; o++) {
            float2 t2;
            memcpy(&t2, &acc[o], 8);
            out[o] = t2.x + t2.y + s_b[o];
        }
        float4 ra = hrow[0], rb = hrow[1];
        float res[8] = {ra.x, ra.y, ra.z, ra.w, rb.x, rb.y, rb.z, rb.w};
        float h8[8];
#pragma unroll
        for (int o = 0; o < 8; o++) {
            float g = s_gb[o];
#pragma unroll
            for (int c = 0; c < 8; c++) g += s_gw[o * 8 + c] * out[c];
            h8[o] = tanhf(out[o]) / (1.f + expf(-g)) + res[o];
        }
        float4* dst = (float4*)(ho + (size_t)(t0 + tl) * CC);
        dst[0] = make_float4(h8[0], h8[1], h8[2], h8[3]);
        dst[1] = make_float4(h8[4], h8[5], h8[6], h8[7]);
    }
}

// ---------------------------------------------------------------------------
// Head: means = mean_w . h + mean_b ; stds = exp(0.5*(lv_w . h + lv_b))
// out[0:B*T] = means, out[B*T:2*B*T] = stds
// ---------------------------------------------------------------------------
__global__ void head_kernel(const float* __restrict__ h,
                            const float* __restrict__ mean_w,
                            const float* __restrict__ mean_b,
                            const float* __restrict__ lv_w,
                            const float* __restrict__ lv_b,
                            float* __restrict__ out) {
    __shared__ float s_mw[8], s_lw[8], s_mb, s_lb;
    if (threadIdx.x < 8) {
        s_mw[threadIdx.x] = mean_w[threadIdx.x];
        s_lw[threadIdx.x] = lv_w[threadIdx.x];
    }
    if (threadIdx.x == 0) { s_mb = mean_b[0]; s_lb = lv_b[0]; }
    __syncthreads();
    size_t i = (size_t)blockIdx.x * blockDim.x + threadIdx.x;
    size_t Ntot = (size_t)BB * TT;
    if (i >= Ntot) return;
    const float4* hp = (const float4*)(h + i * 8);
    float4 a = hp[0], b4 = hp[1];
    float m = s_mb + s_mw[0] * a.x + s_mw[1] * a.y + s_mw[2] * a.z +
              s_mw[3] * a.w + s_mw[4] * b4.x + s_mw[5] * b4.y +
              s_mw[6] * b4.z + s_mw[7] * b4.w;
    float lv = s_lb + s_lw[0] * a.x + s_lw[1] * a.y + s_lw[2] * a.z +
               s_lw[3] * a.w + s_lw[4] * b4.x + s_lw[5] * b4.y +
               s_lw[6] * b4.z + s_lw[7] * b4.w;
    out[i] = m;
    out[Ntot + i] = expf(0.5f * lv);
}

// ---------------------------------------------------------------------------
extern "C" void kernel_launch(void* const* d_in, const int* in_sizes, int n_in,
                              void* d_out, int out_size) {
    const float* x = (const float*)d_in[0];
    const float* v0 = (const float*)d_in[1];
    const float* g0 = (const float*)d_in[2];
    const float* b0 = (const float*)d_in[3];
    const float* gw0 = (const float*)d_in[4];
    const float* gb0 = (const float*)d_in[5];
    const float* vs = (const float*)d_in[6];
    const float* gs = (const float*)d_in[7];
    const float* bs = (const float*)d_in[8];
    const float* gws = (const float*)d_in[9];
    const float* gbs = (const float*)d_in[10];
    const float* mean_w = (const float*)d_in[11];
    const float* mean_b = (const float*)d_in[12];
    const float* lv_w = (const float*)d_in[13];
    const float* lv_b = (const float*)d_in[14];

    float *bufA, *bufB;
    cudaGetSymbolAddress((void**)&bufA, g_bufA);
    cudaGetSymbolAddress((void**)&bufB, g_bufB);

    prep_weights<<<18, 64>>>(v0, g0, vs, gs);

    dim3 grid(TT / TS, BB);
    layer0_kernel<<<grid, NT>>>(x, b0, gw0, gb0);

    static const int DIL[18] = {1, 1, 1, 1, 1, 1, 1, 2, 2, 2, 2, 4, 4, 4, 4, 8, 8, 8};

    size_t smax = (size_t)(KK * 64 + 80 + (TS + 49 * 8) * 8) * sizeof(float);
    cudaFuncSetAttribute(layer_kernel,
                         cudaFuncAttributeMaxDynamicSharedMemorySize, (int)smax);

    float* cur = bufA;
    float* nxt = bufB;
    for (int l = 1; l < 18; l++) {
        int d = DIL[l];
        size_t sm = (size_t)(KK * 64 + 80 + (TS + 49 * d) * 8) * sizeof(float);
        layer_kernel<<<grid, NT, sm>>>(cur, nxt, l - 1, bs + (l - 1) * 8,
                                       gws + (l - 1) * 64, gbs + (l - 1) * 8, d);
        float* t = cur;
        cur = nxt;
        nxt = t;
    }

    head_kernel<<<(int)(((size_t)BB * TT + 255) / 256), 256>>>(
        cur, mean_w, mean_b, lv_w, lv_b, (float*)d_out);
}

// round 3
// speedup vs baseline: 1.9098x; 1.9098x over previous
#include <cuda_runtime.h>
#include <math.h>

#define BB 8
#define TT 262144
#define CC 8
#define KK 50

// layer kernel tiling
#define NT 128
#define TS 1024
#define TREG 4
#define SH 12  // padded row stride in floats (48B): conflict-free LDS.128

// layer0 tiling
#define NT0 256
#define TS0 2048

// Scratch: ping-pong activation buffers [B][T][C] + normalized weights.
__device__ float g_bufA[(size_t)BB * TT * CC];
__device__ float g_bufB[(size_t)BB * TT * CC];
__device__ float g_w[(size_t)17 * KK * CC * CC];  // [layer][k][o][c], tap-reversed
__device__ float g_w0[CC * KK];                   // [o][k], tap-reversed

// ---------------------------------------------------------------------------
// packed fp32x2 FMA (sm_100+): d = a*b + d elementwise on two f32 lanes
// ---------------------------------------------------------------------------
__device__ __forceinline__ void ffma2(unsigned long long& d,
                                      unsigned long long a,
                                      unsigned long long b) {
    asm("fma.rn.f32x2 %0, %1, %2, %0;" : "+l"(d) : "l"(a), "l"(b));
}

// ---------------------------------------------------------------------------
// Weight-norm prep: w[o,c,k] = g[o] * v[o,c,k] / ||v[o,:,:]||, stored
// tap-reversed ([k] slot holds original tap K-1-k) because lax.conv is
// cross-correlation with left-pad (K-1)*d.
// ---------------------------------------------------------------------------
__global__ void prep_weights(const float* __restrict__ v0,
                             const float* __restrict__ g0,
                             const float* __restrict__ vs,
                             const float* __restrict__ gs) {
    __shared__ float rnorm[CC];
    int l = blockIdx.x;
    int tid = threadIdx.x;
    if (l == 0) {
        if (tid < CC) {
            float s = 0.f;
            for (int k = 0; k < KK; k++) {
                float v = v0[tid * KK + k];
                s += v * v;
            }
            rnorm[tid] = rsqrtf(s);
        }
        __syncthreads();
        for (int idx = tid; idx < CC * KK; idx += blockDim.x) {
            int o = idx / KK, k = idx % KK;
            g_w0[o * KK + k] = g0[o] * v0[o * KK + (KK - 1 - k)] * rnorm[o];
        }
    } else {
        int i = l - 1;
        const float* v = vs + (size_t)i * CC * CC * KK;
        if (tid < CC) {
            float s = 0.f;
            for (int j = 0; j < CC * KK; j++) {
                float x = v[tid * CC * KK + j];
                s += x * x;
            }
            rnorm[tid] = rsqrtf(s);
        }
        __syncthreads();
        float* wout = g_w + (size_t)i * KK * CC * CC;
        for (int idx = tid; idx < KK * CC * CC; idx += blockDim.x) {
            int k = idx / (CC * CC);
            int r = idx % (CC * CC);
            int o = r / CC, c = r % CC;
            wout[idx] = gs[i * CC + o] * v[(o * CC + c) * KK + (KK - 1 - k)] * rnorm[o];
        }
    }
}

// ---------------------------------------------------------------------------
// Layer 0: C_in = 1 (x broadcast), dilation 1. Writes g_bufA [B][T][C].
// ---------------------------------------------------------------------------
__global__ void __launch_bounds__(NT0) layer0_kernel(
    const float* __restrict__ x, const float* __restrict__ b0,
    const float* __restrict__ gw0, const float* __restrict__ gb0) {
    __shared__ float s_x[TS0 + KK];
    __shared__ float s_w[CC * KK];
    __shared__ float s_b[CC], s_gb[CC], s_gw[CC * CC];
    int b = blockIdx.y;
    int t0 = blockIdx.x * TS0;
    int tid = threadIdx.x;
    for (int i = tid; i < CC * KK; i += NT0) s_w[i] = g_w0[i];
    for (int i = tid; i < CC * CC; i += NT0) s_gw[i] = gw0[i];
    if (tid < CC) { s_b[tid] = b0[tid]; s_gb[tid] = gb0[tid]; }
    const float* xb = x + (size_t)b * TT;
    for (int i = tid; i < TS0 + KK - 1; i += NT0) {
        int t = t0 - (KK - 1) + i;
        s_x[i] = (t >= 0) ? xb[t] : 0.f;
    }
    __syncthreads();
    float* hout = g_bufA + (size_t)b * TT * CC;
    for (int p = 0; p < TS0 / NT0; p++) {
        int tl = p * NT0 + tid;
        int j = tl + KK - 1;
        float out[CC];
#pragma unroll
        for (int o = 0; o < CC; o++) out[o] = s_b[o];
#pragma unroll 2
        for (int k = 0; k < KK; k++) {
            float xv = s_x[j - k];
#pragma unroll
            for (int o = 0; o < CC; o++) out[o] += s_w[o * KK + k] * xv;
        }
        float res = s_x[j];
        float h8[CC];
#pragma unroll
        for (int o = 0; o < CC; o++) {
            float g = s_gb[o];
#pragma unroll
            for (int c = 0; c < CC; c++) g += s_gw[o * CC + c] * out[c];
            h8[o] = tanhf(out[o]) / (1.f + expf(-g)) + res;
        }
        float4* dst = (float4*)(hout + (size_t)(t0 + tl) * CC);
        dst[0] = make_float4(h8[0], h8[1], h8[2], h8[3]);
        dst[1] = make_float4(h8[4], h8[5], h8[6], h8[7]);
    }
}

// ---------------------------------------------------------------------------
// Layers 1..17: fused dilated causal conv (C=8, K=50) + gating + residual.
// v2: 48B-padded s_h rows (bank-conflict-free LDS.128) + 4-step time register
// blocking so weight loads amortize 4x. f32x2-packed over channel pairs.
// ---------------------------------------------------------------------------
__global__ void __launch_bounds__(NT, 2) layer_kernel(
    const float* __restrict__ hin, float* __restrict__ hout, int li,
    const float* __restrict__ bias, const float* __restrict__ gw,
    const float* __restrict__ gb, int d) {
    extern __shared__ float smem[];
    float* s_w = smem;               // KK*64  [k][o][c]
    float* s_gw = s_w + KK * 64;     // 64
    float* s_b = s_gw + 64;          // 8
    float* s_gb = s_b + 8;           // 8
    float* s_h = s_gb + 8;           // (TS+halo) rows, stride SH=12 floats

    int halo = 49 * d;
    int tid = threadIdx.x;
    int b = blockIdx.y;
    int t0 = blockIdx.x * TS;

    const float* wsrc = g_w + (size_t)li * KK * 64;
    for (int i = tid; i < KK * 64; i += NT) s_w[i] = wsrc[i];
    for (int i = tid; i < 64; i += NT) s_gw[i] = gw[i];
    if (tid < 8) { s_b[tid] = bias[tid]; s_gb[tid] = gb[tid]; }

    const float* hb = hin + (size_t)b * TT * CC;
    int rows = TS + halo;
    for (int i = tid; i < rows * 2; i += NT) {
        int r = i >> 1, half = i & 1;
        int t = t0 - halo + r;
        float4 v = make_float4(0.f, 0.f, 0.f, 0.f);
        if (t >= 0) v = *(const float4*)(hb + (size_t)t * CC + half * 4);
        *(float4*)(s_h + (size_t)r * SH + half * 4) = v;
    }
    __syncthreads();

    float* ho = hout + (size_t)b * TT * CC;
    int step4 = 3 * d;  // k-step in float4 units (SH/4 * d)

    for (int p = 0; p < TS / (NT * TREG); p++) {
        int jbase = p * (NT * TREG) + tid + halo;  // row of r=0 output

        unsigned long long acc[TREG][8];
#pragma unroll
        for (int r = 0; r < TREG; r++)
#pragma unroll
            for (int o = 0; o < 8; o++) acc[r][o] = 0ULL;

        const float4* hp[TREG];
#pragma unroll
        for (int r = 0; r < TREG; r++)
            hp[r] = (const float4*)(s_h + (size_t)(jbase + r * NT) * SH);

#pragma unroll 1
        for (int k = 0; k < KK; k++) {
            unsigned long long h[TREG][4];
#pragma unroll
            for (int r = 0; r < TREG; r++) {
                float4 ha = hp[r][0], hc = hp[r][1];
                memcpy(&h[r][0], &ha.x, 8);
                memcpy(&h[r][1], &ha.z, 8);
                memcpy(&h[r][2], &hc.x, 8);
                memcpy(&h[r][3], &hc.z, 8);
            }
            const float4* wk = (const float4*)(s_w + k * 64);
#pragma unroll
            for (int o = 0; o < 8; o++) {
                float4 wa = wk[o * 2], wb = wk[o * 2 + 1];
                unsigned long long w01, w23, w45, w67;
                memcpy(&w01, &wa.x, 8);
                memcpy(&w23, &wa.z, 8);
                memcpy(&w45, &wb.x, 8);
                memcpy(&w67, &wb.z, 8);
#pragma unroll
                for (int r = 0; r < TREG; r++) {
                    ffma2(acc[r][o], h[r][0], w01);
                    ffma2(acc[r][o], h[r][1], w23);
                    ffma2(acc[r][o], h[r][2], w45);
                    ffma2(acc[r][o], h[r][3], w67);
                }
            }
#pragma unroll
            for (int r = 0; r < TREG; r++) hp[r] -= step4;
        }

#pragma unroll
        for (int r = 0; r < TREG; r++) {
            float out[8];
#pragma unroll
            for (int o = 0; o < 8; o++) {
                float2 t2;
                memcpy(&t2, &acc[r][o], 8);
                out[o] = t2.x + t2.y + s_b[o];
            }
            const float4* hres =
                (const float4*)(s_h + (size_t)(jbase + r * NT) * SH);
            float4 ra = hres[0], rb = hres[1];
            float res[8] = {ra.x, ra.y, ra.z, ra.w, rb.x, rb.y, rb.z, rb.w};
            float h8[8];
#pragma unroll
            for (int o = 0; o < 8; o++) {
                float g = s_gb[o];
#pragma unroll
                for (int c = 0; c < 8; c++) g += s_gw[o * 8 + c] * out[c];
                h8[o] = tanhf(out[o]) / (1.f + expf(-g)) + res[o];
            }
            int tg = t0 + p * (NT * TREG) + r * NT + tid;
            float4* dst = (float4*)(ho + (size_t)tg * CC);
            dst[0] = make_float4(h8[0], h8[1], h8[2], h8[3]);
            dst[1] = make_float4(h8[4], h8[5], h8[6], h8[7]);
        }
    }
}

// ---------------------------------------------------------------------------
// Head: means = mean_w . h + mean_b ; stds = exp(0.5*(lv_w . h + lv_b))
// ---------------------------------------------------------------------------
__global__ void head_kernel(const float* __restrict__ h,
                            const float* __restrict__ mean_w,
                            const float* __restrict__ mean_b,
                            const float* __restrict__ lv_w,
                            const float* __restrict__ lv_b,
                            float* __restrict__ out) {
    __shared__ float s_mw[8], s_lw[8], s_mb, s_lb;
    if (threadIdx.x < 8) {
        s_mw[threadIdx.x] = mean_w[threadIdx.x];
        s_lw[threadIdx.x] = lv_w[threadIdx.x];
    }
    if (threadIdx.x == 0) { s_mb = mean_b[0]; s_lb = lv_b[0]; }
    __syncthreads();
    size_t i = (size_t)blockIdx.x * blockDim.x + threadIdx.x;
    size_t Ntot = (size_t)BB * TT;
    if (i >= Ntot) return;
    const float4* hp = (const float4*)(h + i * 8);
    float4 a = hp[0], b4 = hp[1];
    float m = s_mb + s_mw[0] * a.x + s_mw[1] * a.y + s_mw[2] * a.z +
              s_mw[3] * a.w + s_mw[4] * b4.x + s_mw[5] * b4.y +
              s_mw[6] * b4.z + s_mw[7] * b4.w;
    float lv = s_lb + s_lw[0] * a.x + s_lw[1] * a.y + s_lw[2] * a.z +
               s_lw[3] * a.w + s_lw[4] * b4.x + s_lw[5] * b4.y +
               s_lw[6] * b4.z + s_lw[7] * b4.w;
    out[i] = m;
    out[Ntot + i] = expf(0.5f * lv);
}

// ---------------------------------------------------------------------------
extern "C" void kernel_launch(void* const* d_in, const int* in_sizes, int n_in,
                              void* d_out, int out_size) {
    const float* x = (const float*)d_in[0];
    const float* v0 = (const float*)d_in[1];
    const float* g0 = (const float*)d_in[2];
    const float* b0 = (const float*)d_in[3];
    const float* gw0 = (const float*)d_in[4];
    const float* gb0 = (const float*)d_in[5];
    const float* vs = (const float*)d_in[6];
    const float* gs = (const float*)d_in[7];
    const float* bs = (const float*)d_in[8];
    const float* gws = (const float*)d_in[9];
    const float* gbs = (const float*)d_in[10];
    const float* mean_w = (const float*)d_in[11];
    const float* mean_b = (const float*)d_in[12];
    const float* lv_w = (const float*)d_in[13];
    const float* lv_b = (const float*)d_in[14];

    float *bufA, *bufB;
    cudaGetSymbolAddress((void**)&bufA, g_bufA);
    cudaGetSymbolAddress((void**)&bufB, g_bufB);

    prep_weights<<<18, 64>>>(v0, g0, vs, gs);

    layer0_kernel<<<dim3(TT / TS0, BB), NT0>>>(x, b0, gw0, gb0);

    static const int DIL[18] = {1, 1, 1, 1, 1, 1, 1, 2, 2, 2, 2, 4, 4, 4, 4, 8, 8, 8};

    size_t smax =
        (size_t)(KK * 64 + 80 + (TS + 49 * 8) * SH) * sizeof(float);
    cudaFuncSetAttribute(layer_kernel,
                         cudaFuncAttributeMaxDynamicSharedMemorySize, (int)smax);

    dim3 grid(TT / TS, BB);
    float* cur = bufA;
    float* nxt = bufB;
    for (int l = 1; l < 18; l++) {
        int d = DIL[l];
        size_t sm = (size_t)(KK * 64 + 80 + (TS + 49 * d) * SH) * sizeof(float);
        layer_kernel<<<grid, NT, sm>>>(cur, nxt, l - 1, bs + (l - 1) * 8,
                                       gws + (l - 1) * 64, gbs + (l - 1) * 8, d);
        float* t = cur;
        cur = nxt;
        nxt = t;
    }

    head_kernel<<<(int)(((size_t)BB * TT + 255) / 256), 256>>>(
        cur, mean_w, mean_b, lv_w, lv_b, (float*)d_out);
}

// round 4
// speedup vs baseline: 2.2260x; 1.1656x over previous
#include <cuda_runtime.h>
#include <math.h>

#define BB 8
#define TT 262144
#define CC 8
#define KK 50

// layer kernel tiling
#define NT 128
#define TS 512
#define TREG 4
#define SH 12  // padded row stride in floats (48B): conflict-free LDS.128

// layer0 tiling
#define NT0 256
#define TS0 2048

// Scratch: ping-pong activation buffers [B][T][C] + normalized weights.
__device__ float g_bufA[(size_t)BB * TT * CC];
__device__ float g_bufB[(size_t)BB * TT * CC];
__device__ float g_w[(size_t)17 * KK * CC * CC];  // [layer][k][o][c], tap-reversed
__device__ float g_w0[CC * KK];                   // [o][k], tap-reversed

// ---------------------------------------------------------------------------
// packed fp32x2 FMA (sm_100+): d = a*b + d elementwise on two f32 lanes
// ---------------------------------------------------------------------------
__device__ __forceinline__ void ffma2(unsigned long long& d,
                                      unsigned long long a,
                                      unsigned long long b) {
    asm("fma.rn.f32x2 %0, %1, %2, %0;" : "+l"(d) : "l"(a), "l"(b));
}

// Fast, overflow-safe tanh/sigmoid (err ~1e-6, tolerance is 1e-3).
__device__ __forceinline__ float fast_tanh(float x) {
    float e2 = __expf(-2.f * fabsf(x));          // in (0,1], never overflows
    float t = __fdividef(1.f - e2, 1.f + e2);
    return copysignf(t, x);
}
__device__ __forceinline__ float fast_sigmoid(float x) {
    return __fdividef(1.f, 1.f + __expf(-x));    // exp->inf gives exact 0 limit
}

// ---------------------------------------------------------------------------
// Weight-norm prep: w[o,c,k] = g[o] * v[o,c,k] / ||v[o,:,:]||, stored
// tap-reversed ([k] slot holds original tap K-1-k) because lax.conv is
// cross-correlation with left-pad (K-1)*d.
// ---------------------------------------------------------------------------
__global__ void prep_weights(const float* __restrict__ v0,
                             const float* __restrict__ g0,
                             const float* __restrict__ vs,
                             const float* __restrict__ gs) {
    __shared__ float rnorm[CC];
    int l = blockIdx.x;
    int tid = threadIdx.x;
    if (l == 0) {
        if (tid < CC) {
            float s = 0.f;
            for (int k = 0; k < KK; k++) {
                float v = v0[tid * KK + k];
                s += v * v;
            }
            rnorm[tid] = rsqrtf(s);
        }
        __syncthreads();
        for (int idx = tid; idx < CC * KK; idx += blockDim.x) {
            int o = idx / KK, k = idx % KK;
            g_w0[o * KK + k] = g0[o] * v0[o * KK + (KK - 1 - k)] * rnorm[o];
        }
    } else {
        int i = l - 1;
        const float* v = vs + (size_t)i * CC * CC * KK;
        if (tid < CC) {
            float s = 0.f;
            for (int j = 0; j < CC * KK; j++) {
                float x = v[tid * CC * KK + j];
                s += x * x;
            }
            rnorm[tid] = rsqrtf(s);
        }
        __syncthreads();
        float* wout = g_w + (size_t)i * KK * CC * CC;
        for (int idx = tid; idx < KK * CC * CC; idx += blockDim.x) {
            int k = idx / (CC * CC);
            int r = idx % (CC * CC);
            int o = r / CC, c = r % CC;
            wout[idx] = gs[i * CC + o] * v[(o * CC + c) * KK + (KK - 1 - k)] * rnorm[o];
        }
    }
}

// ---------------------------------------------------------------------------
// Layer 0: C_in = 1 (x broadcast), dilation 1. Writes g_bufA [B][T][C].
// ---------------------------------------------------------------------------
__global__ void __launch_bounds__(NT0) layer0_kernel(
    const float* __restrict__ x, const float* __restrict__ b0,
    const float* __restrict__ gw0, const float* __restrict__ gb0) {
    __shared__ float s_x[TS0 + KK];
    __shared__ float s_w[CC * KK];
    __shared__ float s_b[CC], s_gb[CC], s_gw[CC * CC];
    int b = blockIdx.y;
    int t0 = blockIdx.x * TS0;
    int tid = threadIdx.x;
    for (int i = tid; i < CC * KK; i += NT0) s_w[i] = g_w0[i];
    for (int i = tid; i < CC * CC; i += NT0) s_gw[i] = gw0[i];
    if (tid < CC) { s_b[tid] = b0[tid]; s_gb[tid] = gb0[tid]; }
    const float* xb = x + (size_t)b * TT;
    for (int i = tid; i < TS0 + KK - 1; i += NT0) {
        int t = t0 - (KK - 1) + i;
        s_x[i] = (t >= 0) ? xb[t] : 0.f;
    }
    __syncthreads();
    float* hout = g_bufA + (size_t)b * TT * CC;
    for (int p = 0; p < TS0 / NT0; p++) {
        int tl = p * NT0 + tid;
        int j = tl + KK - 1;
        float out[CC];
#pragma unroll
        for (int o = 0; o < CC; o++) out[o] = s_b[o];
#pragma unroll 2
        for (int k = 0; k < KK; k++) {
            float xv = s_x[j - k];
#pragma unroll
            for (int o = 0; o < CC; o++) out[o] += s_w[o * KK + k] * xv;
        }
        float res = s_x[j];
        float h8[CC];
#pragma unroll
        for (int o = 0; o < CC; o++) {
            float g = s_gb[o];
#pragma unroll
            for (int c = 0; c < CC; c++) g += s_gw[o * CC + c] * out[c];
            h8[o] = fast_tanh(out[o]) * fast_sigmoid(g) + res;
        }
        float4* dst = (float4*)(hout + (size_t)(t0 + tl) * CC);
        dst[0] = make_float4(h8[0], h8[1], h8[2], h8[3]);
        dst[1] = make_float4(h8[4], h8[5], h8[6], h8[7]);
    }
}

// ---------------------------------------------------------------------------
// Layers 1..17: fused dilated causal conv (C=8, K=50) + gating + residual.
// v3: TS=512 (3 CTAs/SM at every dilation) + launch_bounds occupancy cap +
// fast epilogue. 48B-padded s_h rows, 4-step time register blocking,
// f32x2-packed over channel pairs.
// ---------------------------------------------------------------------------
__global__ void __launch_bounds__(NT, 3) layer_kernel(
    const float* __restrict__ hin, float* __restrict__ hout, int li,
    const float* __restrict__ bias, const float* __restrict__ gw,
    const float* __restrict__ gb, int d) {
    extern __shared__ float smem[];
    float* s_w = smem;               // KK*64  [k][o][c]
    float* s_gw = s_w + KK * 64;     // 64
    float* s_b = s_gw + 64;          // 8
    float* s_gb = s_b + 8;           // 8
    float* s_h = s_gb + 8;           // (TS+halo) rows, stride SH=12 floats

    int halo = 49 * d;
    int tid = threadIdx.x;
    int b = blockIdx.y;
    int t0 = blockIdx.x * TS;

    const float* wsrc = g_w + (size_t)li * KK * 64;
    for (int i = tid; i < KK * 64; i += NT) s_w[i] = wsrc[i];
    for (int i = tid; i < 64; i += NT) s_gw[i] = gw[i];
    if (tid < 8) { s_b[tid] = bias[tid]; s_gb[tid] = gb[tid]; }

    const float* hb = hin + (size_t)b * TT * CC;
    int rows = TS + halo;
    for (int i = tid; i < rows * 2; i += NT) {
        int r = i >> 1, half = i & 1;
        int t = t0 - halo + r;
        float4 v = make_float4(0.f, 0.f, 0.f, 0.f);
        if (t >= 0) v = *(const float4*)(hb + (size_t)t * CC + half * 4);
        *(float4*)(s_h + (size_t)r * SH + half * 4) = v;
    }
    __syncthreads();

    float* ho = hout + (size_t)b * TT * CC;
    int step4 = 3 * d;  // k-step in float4 units (SH/4 * d)

#pragma unroll 1
    for (int p = 0; p < TS / (NT * TREG); p++) {
        int jbase = p * (NT * TREG) + tid + halo;  // row of r=0 output

        unsigned long long acc[TREG][8];
#pragma unroll
        for (int r = 0; r < TREG; r++)
#pragma unroll
            for (int o = 0; o < 8; o++) acc[r][o] = 0ULL;

        const float4* hp[TREG];
#pragma unroll
        for (int r = 0; r < TREG; r++)
            hp[r] = (const float4*)(s_h + (size_t)(jbase + r * NT) * SH);

#pragma unroll 1
        for (int k = 0; k < KK; k++) {
            unsigned long long h[TREG][4];
#pragma unroll
            for (int r = 0; r < TREG; r++) {
                float4 ha = hp[r][0], hc = hp[r][1];
                memcpy(&h[r][0], &ha.x, 8);
                memcpy(&h[r][1], &ha.z, 8);
                memcpy(&h[r][2], &hc.x, 8);
                memcpy(&h[r][3], &hc.z, 8);
            }
            const float4* wk = (const float4*)(s_w + k * 64);
#pragma unroll
            for (int o = 0; o < 8; o++) {
                float4 wa = wk[o * 2], wb = wk[o * 2 + 1];
                unsigned long long w01, w23, w45, w67;
                memcpy(&w01, &wa.x, 8);
                memcpy(&w23, &wa.z, 8);
                memcpy(&w45, &wb.x, 8);
                memcpy(&w67, &wb.z, 8);
#pragma unroll
                for (int r = 0; r < TREG; r++) {
                    ffma2(acc[r][o], h[r][0], w01);
                    ffma2(acc[r][o], h[r][1], w23);
                    ffma2(acc[r][o], h[r][2], w45);
                    ffma2(acc[r][o], h[r][3], w67);
                }
            }
#pragma unroll
            for (int r = 0; r < TREG; r++) hp[r] -= step4;
        }

#pragma unroll
        for (int r = 0; r < TREG; r++) {
            float out[8];
#pragma unroll
            for (int o = 0; o < 8; o++) {
                float2 t2;
                memcpy(&t2, &acc[r][o], 8);
                out[o] = t2.x + t2.y + s_b[o];
            }
            const float4* hres =
                (const float4*)(s_h + (size_t)(jbase + r * NT) * SH);
            float4 ra = hres[0], rb = hres[1];
            float res[8] = {ra.x, ra.y, ra.z, ra.w, rb.x, rb.y, rb.z, rb.w};
            float h8[8];
#pragma unroll
            for (int o = 0; o < 8; o++) {
                float g = s_gb[o];
#pragma unroll
                for (int c = 0; c < 8; c++) g += s_gw[o * 8 + c] * out[c];
                h8[o] = fast_tanh(out[o]) * fast_sigmoid(g) + res[o];
            }
            int tg = t0 + p * (NT * TREG) + r * NT + tid;
            float4* dst = (float4*)(ho + (size_t)tg * CC);
            dst[0] = make_float4(h8[0], h8[1], h8[2], h8[3]);
            dst[1] = make_float4(h8[4], h8[5], h8[6], h8[7]);
        }
    }
}

// ---------------------------------------------------------------------------
// Head: means = mean_w . h + mean_b ; stds = exp(0.5*(lv_w . h + lv_b))
// ---------------------------------------------------------------------------
__global__ void head_kernel(const float* __restrict__ h,
                            const float* __restrict__ mean_w,
                            const float* __restrict__ mean_b,
                            const float* __restrict__ lv_w,
                            const float* __restrict__ lv_b,
                            float* __restrict__ out) {
    __shared__ float s_mw[8], s_lw[8], s_mb, s_lb;
    if (threadIdx.x < 8) {
        s_mw[threadIdx.x] = mean_w[threadIdx.x];
        s_lw[threadIdx.x] = lv_w[threadIdx.x];
    }
    if (threadIdx.x == 0) { s_mb = mean_b[0]; s_lb = lv_b[0]; }
    __syncthreads();
    size_t i = (size_t)blockIdx.x * blockDim.x + threadIdx.x;
    size_t Ntot = (size_t)BB * TT;
    if (i >= Ntot) return;
    const float4* hp = (const float4*)(h + i * 8);
    float4 a = hp[0], b4 = hp[1];
    float m = s_mb + s_mw[0] * a.x + s_mw[1] * a.y + s_mw[2] * a.z +
              s_mw[3] * a.w + s_mw[4] * b4.x + s_mw[5] * b4.y +
              s_mw[6] * b4.z + s_mw[7] * b4.w;
    float lv = s_lb + s_lw[0] * a.x + s_lw[1] * a.y + s_lw[2] * a.z +
               s_lw[3] * a.w + s_lw[4] * b4.x + s_lw[5] * b4.y +
               s_lw[6] * b4.z + s_lw[7] * b4.w;
    out[i] = m;
    out[Ntot + i] = expf(0.5f * lv);
}

// ---------------------------------------------------------------------------
extern "C" void kernel_launch(void* const* d_in, const int* in_sizes, int n_in,
                              void* d_out, int out_size) {
    const float* x = (const float*)d_in[0];
    const float* v0 = (const float*)d_in[1];
    const float* g0 = (const float*)d_in[2];
    const float* b0 = (const float*)d_in[3];
    const float* gw0 = (const float*)d_in[4];
    const float* gb0 = (const float*)d_in[5];
    const float* vs = (const float*)d_in[6];
    const float* gs = (const float*)d_in[7];
    const float* bs = (const float*)d_in[8];
    const float* gws = (const float*)d_in[9];
    const float* gbs = (const float*)d_in[10];
    const float* mean_w = (const float*)d_in[11];
    const float* mean_b = (const float*)d_in[12];
    const float* lv_w = (const float*)d_in[13];
    const float* lv_b = (const float*)d_in[14];

    float *bufA, *bufB;
    cudaGetSymbolAddress((void**)&bufA, g_bufA);
    cudaGetSymbolAddress((void**)&bufB, g_bufB);

    prep_weights<<<18, 64>>>(v0, g0, vs, gs);

    layer0_kernel<<<dim3(TT / TS0, BB), NT0>>>(x, b0, gw0, gb0);

    static const int DIL[18] = {1, 1, 1, 1, 1, 1, 1, 2, 2, 2, 2, 4, 4, 4, 4, 8, 8, 8};

    size_t smax =
        (size_t)(KK * 64 + 80 + (TS + 49 * 8) * SH) * sizeof(float);
    cudaFuncSetAttribute(layer_kernel,
                         cudaFuncAttributeMaxDynamicSharedMemorySize, (int)smax);

    dim3 grid(TT / TS, BB);
    float* cur = bufA;
    float* nxt = bufB;
    for (int l = 1; l < 18; l++) {
        int d = DIL[l];
        size_t sm = (size_t)(KK * 64 + 80 + (TS + 49 * d) * SH) * sizeof(float);
        layer_kernel<<<grid, NT, sm>>>(cur, nxt, l - 1, bs + (l - 1) * 8,
                                       gws + (l - 1) * 64, gbs + (l - 1) * 8, d);
        float* t = cur;
        cur = nxt;
        nxt = t;
    }

    head_kernel<<<(int)(((size_t)BB * TT + 255) / 256), 256>>>(
        cur, mean_w, mean_b, lv_w, lv_b, (float*)d_out);
}